// round 1
// baseline (speedup 1.0000x reference)
#include <cuda_runtime.h>
#include <math.h>

#define B_       4
#define CIN      256
#define COUT     256
#define HW       64
#define P_       4096           // 64*64 pixels
#define KK       9
#define CK       2304           // CIN*KK

// ---------------- scratch (__device__ globals: allowed; no cudaMalloc) ------
__device__ float  g_wT[CK * COUT];          // 2.36 MB: wT[ck][o]
__device__ float4 g_mw[B_ * P_ * KK];       // 2.36 MB: 4 bilinear weights (mask-premultiplied)
__device__ int4   g_mi[B_ * P_ * KK];       // 2.36 MB: 4 clamped corner indices

// ---------------- kernel 0: transpose w_def -> wT[ck][o] --------------------
__global__ __launch_bounds__(256) void transpose_w(const float* __restrict__ w) {
    int idx = blockIdx.x * 256 + threadIdx.x;     // idx over [COUT*CK)
    if (idx < COUT * CK) {
        int o  = idx / CK;
        int ck = idx - o * CK;
        g_wT[ck * COUT + o] = w[idx];
    }
}

// ---------------- kernel 1: mod conv + bilinear metadata --------------------
// grid (8,8,4): one 8x8 pixel tile per block, per batch.
// 256 threads = 64 pixels x 4 channel-groups (64 ch each).
__global__ __launch_bounds__(256) void mod_conv_meta(const float* __restrict__ x,
                                                     const float* __restrict__ wmod) {
    __shared__ float red[64 * 27 * 4];   // 6912 floats; aliased as weight stage (3888 used)
    __shared__ float modv[64 * 27];      // reduced mod outputs

    const int b  = blockIdx.z;
    const int t  = threadIdx.x;
    const int pl = t & 63;               // pixel-in-tile
    const int g  = t >> 6;               // channel group 0..3
    const int ph = pl >> 3, pw = pl & 7;
    const int ho = blockIdx.y * 8 + ph;
    const int wo = blockIdx.x * 8 + pw;

    float acc[27];
#pragma unroll
    for (int j = 0; j < 27; j++) acc[j] = 0.f;

    float* ws = red;                     // ws[((g*27+j)*4+ci)*9+tap], 3888 floats
    const float* xb = x + ((size_t)b << 20);   // b*CIN*P_

    for (int c0 = 0; c0 < 64; c0 += 4) {
        __syncthreads();
        // stage w_mod[:, {all 4 groups' 4 channels}, :] into smem
        for (int e = t; e < 4 * 27 * 4 * 9; e += 256) {
            int tap = e % 9;  int r = e / 9;
            int ci  = r & 3;  r >>= 2;
            int j   = r % 27; int gg = r / 27;
            ws[e] = wmod[(j * CIN + gg * 64 + c0 + ci) * 9 + tap];
        }
        __syncthreads();
        for (int ci = 0; ci < 4; ci++) {
            const float* xc = xb + ((size_t)(g * 64 + c0 + ci) << 12);
#pragma unroll
            for (int ky = 0; ky < 3; ky++) {
                int yy = ho + ky - 1;
#pragma unroll
                for (int kx = 0; kx < 3; kx++) {
                    int xx = wo + kx - 1;
                    float v = 0.f;
                    if (yy >= 0 && yy < HW && xx >= 0 && xx < HW) v = xc[(yy << 6) + xx];
                    const int tap = ky * 3 + kx;
#pragma unroll
                    for (int j = 0; j < 27; j++)
                        acc[j] += v * ws[((g * 27 + j) * 4 + ci) * 9 + tap];
                }
            }
        }
    }
    __syncthreads();
#pragma unroll
    for (int j = 0; j < 27; j++) red[(pl * 27 + j) * 4 + g] = acc[j];
    __syncthreads();
    for (int e = t; e < 64 * 27; e += 256)
        modv[e] = red[e * 4] + red[e * 4 + 1] + red[e * 4 + 2] + red[e * 4 + 3];
    __syncthreads();

    // per-(pixel, tap) bilinear metadata
    for (int e = t; e < 64 * KK; e += 256) {
        int pp = e / 9, k = e - (e / 9) * 9;
        int ky = k / 3, kx = k - ky * 3;
        float dy = modv[pp * 27 + 2 * k];
        float dx = modv[pp * 27 + 2 * k + 1];
        float mz = modv[pp * 27 + 18 + k];
        float m  = 1.f / (1.f + expf(-mz));

        int hh = blockIdx.y * 8 + (pp >> 3);
        int ww = blockIdx.x * 8 + (pp & 7);
        float py = dy + (float)(hh - 1 + ky);
        float px = dx + (float)(ww - 1 + kx);
        float y0f = floorf(py), x0f = floorf(px);
        float fy = py - y0f, fx = px - x0f;
        int y0 = (int)y0f, x0 = (int)x0f;
        int y1 = y0 + 1,  x1 = x0 + 1;

        bool vy0 = (y0 >= 0) & (y0 < HW);
        bool vy1 = (y1 >= 0) & (y1 < HW);
        bool vx0 = (x0 >= 0) & (x0 < HW);
        bool vx1 = (x1 >= 0) & (x1 < HW);
        int cy0 = min(max(y0, 0), HW - 1), cy1 = min(max(y1, 0), HW - 1);
        int cx0 = min(max(x0, 0), HW - 1), cx1 = min(max(x1, 0), HW - 1);

        float4 wv;
        wv.x = (vy0 && vx0) ? (1.f - fy) * (1.f - fx) * m : 0.f;
        wv.y = (vy0 && vx1) ? (1.f - fy) * fx         * m : 0.f;
        wv.z = (vy1 && vx0) ? fy * (1.f - fx)         * m : 0.f;
        wv.w = (vy1 && vx1) ? fy * fx                 * m : 0.f;
        int4 iv;
        iv.x = (cy0 << 6) + cx0;
        iv.y = (cy0 << 6) + cx1;
        iv.z = (cy1 << 6) + cx0;
        iv.w = (cy1 << 6) + cx1;

        int p = hh * HW + ww;
        g_mw[((size_t)b * P_ + p) * KK + k] = wv;
        g_mi[((size_t)b * P_ + p) * KK + k] = iv;
    }
}

// ---------------- kernel 2: fused implicit-im2col GEMM ----------------------
// out[b][o][p] = sum_ck wT[ck][o] * gather(x; meta[b][p][ck%9], c=ck/9) + bias
// BM=64, BN=64, BK=8, 256 threads, 4x4 register tile per thread.
__global__ __launch_bounds__(256) void dconv_gemm(const float* __restrict__ x,
                                                  const float* __restrict__ bias,
                                                  float* __restrict__ out) {
    __shared__ __align__(16) float As[8][64];
    __shared__ __align__(16) float Bs[8][64];
    __shared__ __align__(16) float4 mw[64 * KK];
    __shared__ __align__(16) int4   mi[64 * KK];

    const int b  = blockIdx.z;
    const int m0 = blockIdx.y * 64;
    const int p0 = blockIdx.x * 64;          // one full image row of pixels
    const int t  = threadIdx.x;
    const int tm = (t >> 4) << 2;
    const int tn = (t & 15) << 2;
    const float* xb = x + ((size_t)b << 20);

    // load per-pixel metadata for this n-tile (contiguous in p, k)
    {
        const float4* gw = g_mw + ((size_t)b * P_ + p0) * KK;
        const int4*   gi = g_mi + ((size_t)b * P_ + p0) * KK;
        for (int e = t; e < 64 * KK; e += 256) { mw[e] = gw[e]; mi[e] = gi[e]; }
    }

    float acc[4][4];
#pragma unroll
    for (int i = 0; i < 4; i++)
#pragma unroll
        for (int j = 0; j < 4; j++) acc[i][j] = 0.f;

    for (int ck = 0; ck < CK; ck += 8) {
        __syncthreads();   // covers meta readiness (iter 0) + prior frag reads
        // A-tile: wT rows ck..ck+7, cols m0..m0+63 (coalesced)
        {
            int e = t;
            As[e >> 6][e & 63] = g_wT[(ck + (e >> 6)) * COUT + m0 + (e & 63)];
            e = t + 256;
            As[e >> 6][e & 63] = g_wT[(ck + (e >> 6)) * COUT + m0 + (e & 63)];
        }
        // B-tile: gathered im2col values
#pragma unroll
        for (int i = 0; i < 2; i++) {
            int e  = t + i * 256;
            int kc = e >> 6, p = e & 63;
            int kk = ck + kc;
            int c  = kk / 9;
            int tap = kk - c * 9;
            float4 w = mw[p * 9 + tap];
            int4  ii = mi[p * 9 + tap];
            const float* xc = xb + ((size_t)c << 12);
            Bs[kc][p] = w.x * xc[ii.x] + w.y * xc[ii.y] + w.z * xc[ii.z] + w.w * xc[ii.w];
        }
        __syncthreads();
#pragma unroll
        for (int kc = 0; kc < 8; kc++) {
            float4 a  = *(const float4*)&As[kc][tm];
            float4 bb = *(const float4*)&Bs[kc][tn];
            acc[0][0] += a.x * bb.x; acc[0][1] += a.x * bb.y; acc[0][2] += a.x * bb.z; acc[0][3] += a.x * bb.w;
            acc[1][0] += a.y * bb.x; acc[1][1] += a.y * bb.y; acc[1][2] += a.y * bb.z; acc[1][3] += a.y * bb.w;
            acc[2][0] += a.z * bb.x; acc[2][1] += a.z * bb.y; acc[2][2] += a.z * bb.z; acc[2][3] += a.z * bb.w;
            acc[3][0] += a.w * bb.x; acc[3][1] += a.w * bb.y; acc[3][2] += a.w * bb.z; acc[3][3] += a.w * bb.w;
        }
    }

#pragma unroll
    for (int i = 0; i < 4; i++) {
        float bv = bias[m0 + tm + i];
#pragma unroll
        for (int j = 0; j < 4; j++)
            out[((size_t)(b * COUT + m0 + tm + i) << 12) + p0 + tn + j] = acc[i][j] + bv;
    }
}

// ---------------- launch ----------------------------------------------------
extern "C" void kernel_launch(void* const* d_in, const int* in_sizes, int n_in,
                              void* d_out, int out_size) {
    const float* x     = (const float*)d_in[0];   // (4,256,64,64)
    const float* w_mod = (const float*)d_in[1];   // (27,256,3,3)
    const float* w_def = (const float*)d_in[2];   // (256,256,3,3)
    const float* b_def = (const float*)d_in[3];   // (256,)
    float* out = (float*)d_out;                   // (4,256,64,64)

    transpose_w<<<(COUT * CK + 255) / 256, 256>>>(w_def);
    mod_conv_meta<<<dim3(8, 8, B_), 256>>>(x, w_mod);
    dconv_gemm<<<dim3(P_ / 64, COUT / 64, B_), 256>>>(x, b_def, out);
}

// round 4
// speedup vs baseline: 1.7577x; 1.7577x over previous
#include <cuda_runtime.h>
#include <cuda_bf16.h>
#include <math.h>
#include <stdint.h>

#define B_       4
#define CIN      256
#define COUT     256
#define HW       64
#define P_       4096
#define KK       9
#define CK       2304
#define KC       32
#define NITER    (CK / KC)       // 72

// ---------------- scratch ----------------------------------------------------
// A image: per iter 32KB: part(2:hi/lo) x 16KB, tile-major for ldmatrix.
__device__ __align__(128) unsigned char g_wA[NITER * 32768];   // 2.36 MB
__device__ float4 g_mw[B_ * P_ * KK];
__device__ int4   g_mi[B_ * P_ * KK];

// ---------------- PTX helpers (portable ISA only: sm_80/90) ------------------
__device__ __forceinline__ uint32_t smem_u32(const void* p) {
    uint32_t a;
    asm("{ .reg .u64 t; cvta.to.shared.u64 t, %1; cvt.u32.u64 %0, t; }" : "=r"(a) : "l"(p));
    return a;
}
__device__ __forceinline__ void ldsm4(uint32_t* r, uint32_t addr) {
    asm volatile("ldmatrix.sync.aligned.m8n8.x4.shared.b16 {%0,%1,%2,%3}, [%4];"
                 : "=r"(r[0]), "=r"(r[1]), "=r"(r[2]), "=r"(r[3]) : "r"(addr));
}
__device__ __forceinline__ void mma_bf16(float* d, const uint32_t* a, const uint32_t* b) {
    asm volatile("mma.sync.aligned.m16n8k16.row.col.f32.bf16.bf16.f32 "
                 "{%0,%1,%2,%3}, {%4,%5,%6,%7}, {%8,%9}, {%0,%1,%2,%3};"
                 : "+f"(d[0]), "+f"(d[1]), "+f"(d[2]), "+f"(d[3])
                 : "r"(a[0]), "r"(a[1]), "r"(a[2]), "r"(a[3]), "r"(b[0]), "r"(b[1]));
}
__device__ __forceinline__ void cpasync16(uint32_t dst, const void* src) {
    asm volatile("cp.async.cg.shared.global [%0], [%1], 16;" :: "r"(dst), "l"(src));
}
#define CP_COMMIT()  asm volatile("cp.async.commit_group;" ::: "memory")
#define CP_WAIT(n)   asm volatile("cp.async.wait_group %0;" :: "n"(n) : "memory")

// ---------------- smem layout (dynamic, 175104 B) ----------------------------
#define AS_OFF   0                 // 3 stages x 32768 (part hi at +0, lo at +16384)
#define BS_OFF   98304             // 3 stages x 16384 (hi at +0, lo at +8192)
#define MW_OFF   147456            // float4[1152]
#define MI_OFF   165888            // ushort4[1152]
#define SMEM_BYTES 175104

// ---------------- kernel 0: prep A (bf16 split, ldmatrix tile-major) ---------
// tile-major: byte = it*32768 + part*16384 + ((Mblk*2+Kb)*4 + a_idx)*128
//                    + (o&7)*16 + (kl&7)*2
__global__ __launch_bounds__(256) void prep_wA(const float* __restrict__ w) {
    int idx = blockIdx.x * 256 + threadIdx.x;
    if (idx >= COUT * CK) return;
    int o = idx / CK, ck = idx - o * CK;
    float v = w[idx];
    __nv_bfloat16 hb = __float2bfloat16(v);
    __nv_bfloat16 lb = __float2bfloat16(v - __bfloat162float(hb));
    int it = ck >> 5, kl = ck & 31;
    int Mblk = o >> 4, Kb = (kl >> 4) & 1;
    int a_idx = ((o >> 3) & 1) + 2 * ((kl >> 3) & 1);
    uint32_t byte = (uint32_t)it * 32768u
                  + (uint32_t)(((Mblk * 2 + Kb) * 4 + a_idx) * 128)
                  + (uint32_t)((o & 7) * 16 + (kl & 7) * 2);
    *(unsigned short*)(g_wA + byte)         = __bfloat16_as_ushort(hb);
    *(unsigned short*)(g_wA + byte + 16384) = __bfloat16_as_ushort(lb);
}

// ---------------- kernel 1: mod conv + bilinear metadata (unchanged) --------
__global__ __launch_bounds__(256) void mod_conv_meta(const float* __restrict__ x,
                                                     const float* __restrict__ wmod) {
    __shared__ float red[64 * 27 * 4];
    __shared__ float modv[64 * 27];

    const int b  = blockIdx.z;
    const int t  = threadIdx.x;
    const int pl = t & 63;
    const int g  = t >> 6;
    const int ph = pl >> 3, pw = pl & 7;
    const int ho = blockIdx.y * 8 + ph;
    const int wo = blockIdx.x * 8 + pw;

    float acc[27];
#pragma unroll
    for (int j = 0; j < 27; j++) acc[j] = 0.f;

    float* ws = red;
    const float* xb = x + ((size_t)b << 20);

    for (int c0 = 0; c0 < 64; c0 += 4) {
        __syncthreads();
        for (int e = t; e < 4 * 27 * 4 * 9; e += 256) {
            int tap = e % 9;  int r = e / 9;
            int ci  = r & 3;  r >>= 2;
            int j   = r % 27; int gg = r / 27;
            ws[e] = wmod[(j * CIN + gg * 64 + c0 + ci) * 9 + tap];
        }
        __syncthreads();
        for (int ci = 0; ci < 4; ci++) {
            const float* xc = xb + ((size_t)(g * 64 + c0 + ci) << 12);
#pragma unroll
            for (int ky = 0; ky < 3; ky++) {
                int yy = ho + ky - 1;
#pragma unroll
                for (int kx = 0; kx < 3; kx++) {
                    int xx = wo + kx - 1;
                    float v = 0.f;
                    if (yy >= 0 && yy < HW && xx >= 0 && xx < HW) v = xc[(yy << 6) + xx];
                    const int tap = ky * 3 + kx;
#pragma unroll
                    for (int j = 0; j < 27; j++)
                        acc[j] += v * ws[((g * 27 + j) * 4 + ci) * 9 + tap];
                }
            }
        }
    }
    __syncthreads();
#pragma unroll
    for (int j = 0; j < 27; j++) red[(pl * 27 + j) * 4 + g] = acc[j];
    __syncthreads();
    for (int e = t; e < 64 * 27; e += 256)
        modv[e] = red[e * 4] + red[e * 4 + 1] + red[e * 4 + 2] + red[e * 4 + 3];
    __syncthreads();

    for (int e = t; e < 64 * KK; e += 256) {
        int pp = e / 9, k = e - (e / 9) * 9;
        int ky = k / 3, kx = k - ky * 3;
        float dy = modv[pp * 27 + 2 * k];
        float dx = modv[pp * 27 + 2 * k + 1];
        float mz = modv[pp * 27 + 18 + k];
        float m  = 1.f / (1.f + expf(-mz));

        int hh = blockIdx.y * 8 + (pp >> 3);
        int ww = blockIdx.x * 8 + (pp & 7);
        float py = dy + (float)(hh - 1 + ky);
        float px = dx + (float)(ww - 1 + kx);
        float y0f = floorf(py), x0f = floorf(px);
        float fy = py - y0f, fx = px - x0f;
        int y0 = (int)y0f, x0 = (int)x0f;
        int y1 = y0 + 1,  x1 = x0 + 1;

        bool vy0 = (y0 >= 0) & (y0 < HW);
        bool vy1 = (y1 >= 0) & (y1 < HW);
        bool vx0 = (x0 >= 0) & (x0 < HW);
        bool vx1 = (x1 >= 0) & (x1 < HW);
        int cy0 = min(max(y0, 0), HW - 1), cy1 = min(max(y1, 0), HW - 1);
        int cx0 = min(max(x0, 0), HW - 1), cx1 = min(max(x1, 0), HW - 1);

        float4 wv;
        wv.x = (vy0 && vx0) ? (1.f - fy) * (1.f - fx) * m : 0.f;
        wv.y = (vy0 && vx1) ? (1.f - fy) * fx         * m : 0.f;
        wv.z = (vy1 && vx0) ? fy * (1.f - fx)         * m : 0.f;
        wv.w = (vy1 && vx1) ? fy * fx                 * m : 0.f;
        int4 iv;
        iv.x = (cy0 << 6) + cx0;
        iv.y = (cy0 << 6) + cx1;
        iv.z = (cy1 << 6) + cx0;
        iv.w = (cy1 << 6) + cx1;

        int p = hh * HW + ww;
        g_mw[((size_t)b * P_ + p) * KK + k] = wv;
        g_mi[((size_t)b * P_ + p) * KK + k] = iv;
    }
}

// ---------------- kernel 2: HMMA implicit-im2col GEMM ------------------------
// CTA: M=256, N=128px. 512 thr = 16 warps (8 in M x 2 in N), warp tile 32x64.
// Triple-buffered A (cp.async) and B (gather) stages, KC=32, 72 iters, 3-pass bf16.
__global__ __launch_bounds__(512, 1) void dconv_tc(const float* __restrict__ x,
                                                   const float* __restrict__ bias,
                                                   float* __restrict__ out) {
    extern __shared__ __align__(1024) unsigned char sm[];
    const uint32_t sb = smem_u32(sm);
    const int t  = threadIdx.x;
    const int b  = blockIdx.z;
    const int p0 = blockIdx.x * 128;
    const float* xb = x + ((size_t)b << 20);

    const int lane = t & 31, warp = t >> 5;
    const int wm = warp >> 1, wn = warp & 1;

    // stage meta
    float4*  s_mw = (float4*)(sm + MW_OFF);
    ushort4* s_mi = (ushort4*)(sm + MI_OFF);
    {
        const float4* gw = g_mw + ((size_t)b * P_ + p0) * KK;
        const int4*   gi = g_mi + ((size_t)b * P_ + p0) * KK;
        for (int e = t; e < 128 * KK; e += 512) {
            s_mw[e] = gw[e];
            int4 v = gi[e];
            s_mi[e] = make_ushort4((unsigned short)v.x, (unsigned short)v.y,
                                   (unsigned short)v.z, (unsigned short)v.w);
        }
    }
    __syncthreads();

    float d[2][8][4];
#pragma unroll
    for (int a = 0; a < 2; a++)
#pragma unroll
        for (int c = 0; c < 8; c++)
#pragma unroll
            for (int e = 0; e < 4; e++) d[a][c][e] = 0.f;

    // ---- producer: stage s=(i%3): A via cp.async, B via gather+STS ----------
    auto produce = [&](int i) {
        const int s = i % 3;
        // A: 32KB copy, 64B per thread
        {
            uint32_t dst = sb + AS_OFF + s * 32768 + t * 64;
            const unsigned char* src = g_wA + (size_t)i * 32768 + t * 64;
#pragma unroll
            for (int q = 0; q < 4; q++) cpasync16(dst + q * 16, src + q * 16);
            CP_COMMIT();
        }
        // B: gather 32ck x 128p, bf16 hi/lo, tile-major
        const int ck0 = i * KC;
        unsigned char* bh = sm + BS_OFF + s * 16384;
        unsigned char* bl = bh + 8192;
#pragma unroll
        for (int j = 0; j < 4; j++) {
            int e  = t + j * 512;
            int p  = e >> 4;
            int pp = e & 15;              // pair position: ckl = pp*2
            int ckl = pp * 2;
            int kk  = ck0 + ckl;
            int c0  = (kk * 7282) >> 16;        int tap0 = kk - c0 * 9;
            int kk1 = kk + 1;
            int c1  = (kk1 * 7282) >> 16;       int tap1 = kk1 - c1 * 9;
            float4  w0 = s_mw[p * 9 + tap0];    ushort4 i0 = s_mi[p * 9 + tap0];
            float4  w1 = s_mw[p * 9 + tap1];    ushort4 i1 = s_mi[p * 9 + tap1];
            const float* xc0 = xb + ((size_t)c0 << 12);
            const float* xc1 = xb + ((size_t)c1 << 12);
            float g0 = w0.x * __ldg(xc0 + i0.x) + w0.y * __ldg(xc0 + i0.y)
                     + w0.z * __ldg(xc0 + i0.z) + w0.w * __ldg(xc0 + i0.w);
            float g1 = w1.x * __ldg(xc1 + i1.x) + w1.y * __ldg(xc1 + i1.y)
                     + w1.z * __ldg(xc1 + i1.z) + w1.w * __ldg(xc1 + i1.w);
            __nv_bfloat16 h0 = __float2bfloat16(g0);
            __nv_bfloat16 h1 = __float2bfloat16(g1);
            __nv_bfloat16 l0 = __float2bfloat16(g0 - __bfloat162float(h0));
            __nv_bfloat16 l1 = __float2bfloat16(g1 - __bfloat162float(h1));
            uint32_t hiw = ((uint32_t)__bfloat16_as_ushort(h1) << 16) | __bfloat16_as_ushort(h0);
            uint32_t low = ((uint32_t)__bfloat16_as_ushort(l1) << 16) | __bfloat16_as_ushort(l0);
            // tile-major: nt=p/8, kt=ckl/8
            uint32_t byte = (uint32_t)(((p >> 3) * 4 + (pp >> 2)) * 128
                                       + (p & 7) * 16 + (pp & 3) * 4);
            *(uint32_t*)(bh + byte) = hiw;
            *(uint32_t*)(bl + byte) = low;
        }
    };

    // ---- consumer: ldmatrix + mma for iter i --------------------------------
    auto consume = [&](int i) {
        const uint32_t as = sb + AS_OFF + (i % 3) * 32768;
        const uint32_t bs = sb + BS_OFF + (i % 3) * 16384;
        const uint32_t arow = (uint32_t)((lane & 7) * 16);
        const uint32_t gsel = (uint32_t)(lane >> 3);
#pragma unroll
        for (int kb = 0; kb < 2; kb++) {
            uint32_t ahi[8], alo[8];
#pragma unroll
            for (int mb = 0; mb < 2; mb++) {
                uint32_t tb = (uint32_t)((((wm * 2 + mb) * 2 + kb) * 4 + gsel) * 128) + arow;
                ldsm4(ahi + mb * 4, as + tb);
                ldsm4(alo + mb * 4, as + 16384 + tb);
            }
#pragma unroll
            for (int jj = 0; jj < 4; jj++) {
                int nt = wn * 8 + jj * 2;
                uint32_t tb = (uint32_t)(((nt + (gsel >> 1)) * 4 + 2 * kb + (gsel & 1)) * 128) + arow;
                uint32_t bhi[4], blo[4];
                ldsm4(bhi, bs + tb);
                ldsm4(blo, bs + 8192 + tb);
#pragma unroll
                for (int mb = 0; mb < 2; mb++) {
#pragma unroll
                    for (int nn = 0; nn < 2; nn++) {
                        float* dd = d[mb][jj * 2 + nn];
                        mma_bf16(dd, ahi + mb * 4, bhi + nn * 2);
                        mma_bf16(dd, ahi + mb * 4, blo + nn * 2);
                        mma_bf16(dd, alo + mb * 4, bhi + nn * 2);
                    }
                }
            }
        }
    };

    produce(0);
    for (int i = 0; i < NITER; i++) {
        if (i + 1 < NITER) { produce(i + 1); CP_WAIT(1); }
        else               { CP_WAIT(0); }
        __syncthreads();
        consume(i);
    }

    // ---- epilogue -----------------------------------------------------------
#pragma unroll
    for (int mb = 0; mb < 2; mb++) {
        int m0 = wm * 32 + mb * 16 + (lane >> 2);
        float bv0 = bias[m0], bv1 = bias[m0 + 8];
        float* r0 = out + (((size_t)(b * COUT + m0)) << 12) + p0 + wn * 64 + (lane & 3) * 2;
        float* r1 = r0 + ((size_t)8 << 12);
#pragma unroll
        for (int nj = 0; nj < 8; nj++) {
            float2 v0 = make_float2(d[mb][nj][0] + bv0, d[mb][nj][1] + bv0);
            float2 v1 = make_float2(d[mb][nj][2] + bv1, d[mb][nj][3] + bv1);
            *(float2*)(r0 + nj * 8) = v0;
            *(float2*)(r1 + nj * 8) = v1;
        }
    }
}

// ---------------- launch ------------------------------------------------------
extern "C" void kernel_launch(void* const* d_in, const int* in_sizes, int n_in,
                              void* d_out, int out_size) {
    const float* x     = (const float*)d_in[0];
    const float* w_mod = (const float*)d_in[1];
    const float* w_def = (const float*)d_in[2];
    const float* b_def = (const float*)d_in[3];
    float* out = (float*)d_out;

    cudaFuncSetAttribute(dconv_tc, cudaFuncAttributeMaxDynamicSharedMemorySize, SMEM_BYTES);

    prep_wA<<<(COUT * CK + 255) / 256, 256>>>(w_def);
    mod_conv_meta<<<dim3(8, 8, B_), 256>>>(x, w_mod);
    dconv_tc<<<dim3(P_ / 128, 1, B_), 512, SMEM_BYTES>>>(x, b_def, out);
}